// round 14
// baseline (speedup 1.0000x reference)
#include <cuda_runtime.h>
#include <math.h>
#include <cstdint>

#define NNODES 100000
#define NCELLS 200000
#define NEDGES 300000
#define DIM 128
#define THREEC (3*NCELLS)

// ---------------- scratch (static device globals: allocation-free) ----------
__device__ float g_nodesum[NNODES];
__device__ float g_counts[NNODES];
__device__ float g_nodeagg[(size_t)NNODES * DIM];

// ---------------- helpers ----------------
__device__ __forceinline__ uint32_t rna(float x) {
    uint32_t u; asm("cvt.rna.tf32.f32 %0, %1;" : "=r"(u) : "f"(x)); return u;
}
__device__ __forceinline__ float rnaf(float x) { return __uint_as_float(rna(x)); }

__device__ __forceinline__ void mma8(float c[4], const uint32_t a[4], const uint32_t b[2]) {
    asm volatile("mma.sync.aligned.m16n8k8.row.col.f32.tf32.tf32.f32 "
        "{%0,%1,%2,%3}, {%4,%5,%6,%7}, {%8,%9}, {%0,%1,%2,%3};"
        : "+f"(c[0]), "+f"(c[1]), "+f"(c[2]), "+f"(c[3])
        : "r"(a[0]), "r"(a[1]), "r"(a[2]), "r"(a[3]), "r"(b[0]), "r"(b[1]));
}

// ---------------- zero init ----------------
__global__ void zero_kernel(float* __restrict__ node_out) {
    int i = blockIdx.x * 256 + threadIdx.x;
    if (i < NNODES * DIM) { g_nodeagg[i] = 0.f; node_out[i] = 0.f; }
    if (i < NNODES)       { g_nodesum[i] = 0.f; g_counts[i] = 0.f; }
}

// ---------------- fused attention: one warp per EDGE, both directions -------
__global__ void attn_kernel(const float* __restrict__ edge_attr,
                            const float* __restrict__ node_emb,
                            const int*   __restrict__ edge_index) {
    int e    = (blockIdx.x * blockDim.x + threadIdx.x) >> 5;
    int lane = threadIdx.x & 31;
    if (e >= NEDGES) return;
    int s = __ldg(edge_index + e);
    int r = __ldg(edge_index + NEDGES + e);

    float4 a  = __ldg(((const float4*)edge_attr) + (size_t)e * 32 + lane);
    float4 bs = __ldg(((const float4*)node_emb)  + (size_t)s * 32 + lane);
    float4 br = __ldg(((const float4*)node_emb)  + (size_t)r * 32 + lane);
    float ds = a.x * bs.x + a.y * bs.y + a.z * bs.z + a.w * bs.w;
    float dr = a.x * br.x + a.y * br.y + a.z * br.z + a.w * br.w;
    #pragma unroll
    for (int off = 16; off > 0; off >>= 1) {
        ds += __shfl_xor_sync(0xffffffffu, ds, off);
        dr += __shfl_xor_sync(0xffffffffu, dr, off);
    }
    float es = expf(ds * 0.08838834764831845f);   // logits bounded, no max-shift
    float er = expf(dr * 0.08838834764831845f);

    float* dstr = g_nodeagg + (size_t)r * DIM + lane * 4;
    asm volatile("red.global.add.v4.f32 [%0], {%1,%2,%3,%4};"
                 :: "l"(dstr), "f"(a.x * er), "f"(a.y * er), "f"(a.z * er), "f"(a.w * er)
                 : "memory");
    float* dsts = g_nodeagg + (size_t)s * DIM + lane * 4;
    asm volatile("red.global.add.v4.f32 [%0], {%1,%2,%3,%4};"
                 :: "l"(dsts), "f"(a.x * es), "f"(a.y * es), "f"(a.z * es), "f"(a.w * es)
                 : "memory");
    if (lane == 0) atomicAdd(&g_nodesum[r], er);
    if (lane == 1) atomicAdd(&g_nodesum[s], es);
}

// ============================================================================
// fused MLP on tf32 mma.sync
// M-tile=64 (grid 3125 = 200000/64, no bounds checks), 256 threads, 8 warps
// (2 m-warps x 4 n-warps, warp tile 32x32), BK=32, double-buffered A/B.
// h[64x132] overlaps the A double-buffer region (union) -> 71KB SMEM/CTA,
// 2 CTAs/SM for cross-CTA latency hiding.
// ============================================================================
#define LDA 36
#define LDB 136
#define LDH 132
#define MTILE 64
#define A_CH (MTILE*LDA)            // 2304 floats per A buffer
#define B_CH (32*LDB)               // 4352 floats per B buffer
#define UNION_FLOATS (MTILE*LDH)    // 8448 >= 2*A_CH (4608)
#define SB_OFF UNION_FLOATS
#define B1_OFF (SB_OFF + 2*B_CH)
#define B2_OFF (B1_OFF + 128)
#define SF_OFF (B2_OFF + 128)
#define SINV_OFF (SF_OFF + 3*MTILE)
#define SMEM_FLOATS (SINV_OFF + 3*MTILE)
#define MLP_SMEM (SMEM_FLOATS * 4)

__global__ __launch_bounds__(256, 2)
void mlp_mma_kernel(const float* __restrict__ cell_attr, const int* __restrict__ face,
                    const float* __restrict__ W1, const float* __restrict__ b1,
                    const float* __restrict__ W2, const float* __restrict__ b2,
                    float* __restrict__ out) {
    extern __shared__ float sm[];
    float* sA   = sm;                 // 2 x A_CH (within union)
    float* sH   = sm;                 // 64 x LDH (union, after GEMM1)
    float* sB   = sm + SB_OFF;
    float* b1s  = sm + B1_OFF;
    float* b2s  = sm + B2_OFF;
    int*   sF   = (int*)(sm + SF_OFF);
    float* sInv = sm + SINV_OFF;

    const int tid  = threadIdx.x;
    const int wid  = tid >> 5, lane = tid & 31;
    const int g    = lane >> 2, tig = lane & 3;
    const int m0   = (wid & 1) * 32, n0 = (wid >> 1) * 32;
    const int rowBase = blockIdx.x * MTILE;
    const float inv3 = 1.f / 3.f;

    if (tid < 128) { b1s[tid] = b1[tid]; b2s[tid] = b2[tid]; }
    if (tid < MTILE) {
        int r = rowBase + tid;
        #pragma unroll
        for (int q = 0; q < 3; q++) {
            int f = face[q * NCELLS + r];
            sF[q * MTILE + tid] = f;
            float s = g_nodesum[f];
            sInv[q * MTILE + tid] = (s > 0.f) ? (inv3 / s) : 0.f;
        }
    }
    // sF/sInv first consumed by fetchA(c>=4), after several syncs.

    float acc[2][4][4];
    #pragma unroll
    for (int mt = 0; mt < 2; mt++)
        #pragma unroll
        for (int nt = 0; nt < 4; nt++)
            #pragma unroll
            for (int q = 0; q < 4; q++) acc[mt][nt][q] = 0.f;

    float4 pa[2], pb[4];

    // ---- A chunk (64 rows x 32 k): 512 float4, 2 per thread ----
    auto fetchA = [&](int c) {
        #pragma unroll
        for (int h = 0; h < 2; h++) {
            int j = tid + h * 256;               // [0,512)
            int m = j >> 3, kq = (j & 7) * 4;
            float4 v;
            int r = rowBase + m;
            if (c < 4) {
                v = __ldg((const float4*)(cell_attr + (size_t)r * 128 + c * 32 + kq));
            } else {
                int gk = (c - 4) * 32 + kq;
                float i0 = sInv[m], i1 = sInv[MTILE + m], i2 = sInv[2 * MTILE + m];
                float4 a0 = __ldg((const float4*)(g_nodeagg + (size_t)sF[m]           * 128 + gk));
                float4 a1 = __ldg((const float4*)(g_nodeagg + (size_t)sF[MTILE + m]   * 128 + gk));
                float4 a2 = __ldg((const float4*)(g_nodeagg + (size_t)sF[2*MTILE + m] * 128 + gk));
                v.x = a0.x * i0 + a1.x * i1 + a2.x * i2;
                v.y = a0.y * i0 + a1.y * i1 + a2.y * i2;
                v.z = a0.z * i0 + a1.z * i1 + a2.z * i2;
                v.w = a0.w * i0 + a1.w * i1 + a2.w * i2;
            }
            pa[h] = v;
        }
    };
    auto storeA = [&](int buf) {
        float* dst = sA + buf * A_CH;
        #pragma unroll
        for (int h = 0; h < 2; h++) {
            int j = tid + h * 256;
            int m = j >> 3, kq = (j & 7) * 4;
            float4 v;
            v.x = rnaf(pa[h].x); v.y = rnaf(pa[h].y);
            v.z = rnaf(pa[h].z); v.w = rnaf(pa[h].w);
            *(float4*)(dst + m * LDA + kq) = v;   // m-major STS.128, conflict-free
        }
    };
    // ---- B chunk (32 k x 128 n): 1024 float4, 4 per thread ----
    auto fetchB = [&](const float* W, int c) {
        #pragma unroll
        for (int h = 0; h < 4; h++) {
            int j = tid + h * 256;
            int k = j >> 5, n4 = (j & 31) * 4;
            pb[h] = __ldg((const float4*)(W + (size_t)(c * 32 + k) * 128 + n4));
        }
    };
    auto storeB = [&](int buf) {
        float* dst = sB + buf * B_CH;
        #pragma unroll
        for (int h = 0; h < 4; h++) {
            int j = tid + h * 256;
            int k = j >> 5, n4 = (j & 31) * 4;
            float4 v;
            v.x = rnaf(pb[h].x); v.y = rnaf(pb[h].y);
            v.z = rnaf(pb[h].z); v.w = rnaf(pb[h].w);
            *(float4*)(dst + k * LDB + n4) = v;
        }
    };
    auto mmastep = [&](const float* Ab, int lda, const float* Bb) {
        #pragma unroll
        for (int k0 = 0; k0 < 32; k0 += 8) {
            uint32_t af[2][4], bf[4][2];
            #pragma unroll
            for (int mt = 0; mt < 2; mt++) {
                const float* ar = Ab + (m0 + 16 * mt + g) * lda + k0;
                af[mt][0] = __float_as_uint(ar[tig]);
                af[mt][1] = __float_as_uint(ar[8 * lda + tig]);
                af[mt][2] = __float_as_uint(ar[tig + 4]);
                af[mt][3] = __float_as_uint(ar[8 * lda + tig + 4]);
            }
            const float* br = Bb + k0 * LDB;
            #pragma unroll
            for (int nt = 0; nt < 4; nt++) {
                int nn = n0 + 8 * nt + g;
                bf[nt][0] = __float_as_uint(br[tig * LDB + nn]);
                bf[nt][1] = __float_as_uint(br[(tig + 4) * LDB + nn]);
            }
            #pragma unroll
            for (int mt = 0; mt < 2; mt++)
                #pragma unroll
                for (int nt = 0; nt < 4; nt++)
                    mma8(acc[mt][nt], af[mt], bf[nt]);
        }
    };

    // -------- GEMM1: concat(cell_attr, cell_agg)[64x256] @ W1 --------
    fetchA(0); fetchB(W1, 0);
    storeA(0); storeB(0);
    __syncthreads();
    for (int c = 0; c < 8; c++) {
        int buf = c & 1;
        if (c < 7) { fetchA(c + 1); fetchB(W1, c + 1); }
        mmastep(sA + buf * A_CH, LDA, sB + buf * B_CH);
        if (c < 7) {
            storeA(buf ^ 1); storeB(buf ^ 1);
            __syncthreads();
        }
    }
    __syncthreads();   // all warps done reading A bufs before h overwrites union

    // -------- epilogue 1: h = relu(D1 + b1) -> sH (union), tf32-rounded --------
    #pragma unroll
    for (int mt = 0; mt < 2; mt++) {
        int row = m0 + 16 * mt + g;
        #pragma unroll
        for (int nt = 0; nt < 4; nt++) {
            int col = n0 + 8 * nt + 2 * tig;
            float bb0 = b1s[col], bb1 = b1s[col + 1];
            float2 h0, h1;
            h0.x = rnaf(fmaxf(acc[mt][nt][0] + bb0, 0.f));
            h0.y = rnaf(fmaxf(acc[mt][nt][1] + bb1, 0.f));
            h1.x = rnaf(fmaxf(acc[mt][nt][2] + bb0, 0.f));
            h1.y = rnaf(fmaxf(acc[mt][nt][3] + bb1, 0.f));
            *(float2*)(sH + row * LDH + col)       = h0;
            *(float2*)(sH + (row + 8) * LDH + col) = h1;
            acc[mt][nt][0] = 0.f; acc[mt][nt][1] = 0.f;
            acc[mt][nt][2] = 0.f; acc[mt][nt][3] = 0.f;
        }
    }
    fetchB(W2, 0);
    storeB(0);
    __syncthreads();   // covers sH writes + W2 buf0

    // -------- GEMM2: h[64x128] @ W2 --------
    for (int c = 0; c < 4; c++) {
        int buf = c & 1;
        if (c < 3) fetchB(W2, c + 1);
        mmastep(sH + c * 32, LDH, sB + buf * B_CH);
        if (c < 3) {
            storeB(buf ^ 1);
            __syncthreads();
        }
    }

    // -------- epilogue 2: out = D2 + b2 --------
    #pragma unroll
    for (int mt = 0; mt < 2; mt++) {
        int row = m0 + 16 * mt + g;
        float* o0 = out + (size_t)(rowBase + row) * 128;
        float* o1 = out + (size_t)(rowBase + row + 8) * 128;
        #pragma unroll
        for (int nt = 0; nt < 4; nt++) {
            int col = n0 + 8 * nt + 2 * tig;
            *(float2*)(o0 + col) = make_float2(acc[mt][nt][0] + b2s[col],
                                               acc[mt][nt][1] + b2s[col + 1]);
            *(float2*)(o1 + col) = make_float2(acc[mt][nt][2] + b2s[col],
                                               acc[mt][nt][3] + b2s[col + 1]);
        }
    }
}

// ---------------- scatter cell outputs to node sums + counts ----------------
__global__ void scatter_cell_kernel(const float* __restrict__ cell_out,
                                    const int*   __restrict__ face,
                                    float* __restrict__ node_out) {
    int w    = (blockIdx.x * blockDim.x + threadIdx.x) >> 5;
    int lane = threadIdx.x & 31;
    if (w >= THREEC) return;
    int node = face[w];
    int c = w;
    if (c >= NCELLS) c -= NCELLS;
    if (c >= NCELLS) c -= NCELLS;

    float4 v = __ldg(((const float4*)cell_out) + (size_t)c * 32 + lane);
    float* dst = node_out + (size_t)node * DIM + lane * 4;
    asm volatile("red.global.add.v4.f32 [%0], {%1,%2,%3,%4};"
                 :: "l"(dst), "f"(v.x), "f"(v.y), "f"(v.z), "f"(v.w)
                 : "memory");
    if (lane == 0) atomicAdd(&g_counts[node], 1.f);
}

__global__ void finalize_kernel(float* __restrict__ node_out) {
    int i = blockIdx.x * 256 + threadIdx.x;
    if (i >= NNODES * DIM / 4) return;
    float inv = 1.f / fmaxf(g_counts[i >> 5], 1.f);
    float4 v = ((float4*)node_out)[i];
    v.x *= inv; v.y *= inv; v.z *= inv; v.w *= inv;
    ((float4*)node_out)[i] = v;
}

// ---------------- launch ----------------
extern "C" void kernel_launch(void* const* d_in, const int* in_sizes, int n_in,
                              void* d_out, int out_size) {
    const float* cell_attr  = (const float*)d_in[0];
    const float* edge_attr  = (const float*)d_in[1];
    const float* node_emb   = (const float*)d_in[2];
    const int*   edge_index = (const int*)d_in[3];
    const int*   face       = (const int*)d_in[4];
    const float* W1 = (const float*)d_in[5];
    const float* b1 = (const float*)d_in[6];
    const float* W2 = (const float*)d_in[7];
    const float* b2 = (const float*)d_in[8];

    float* out      = (float*)d_out;
    float* cell_out = out;
    float* node_out = out + (size_t)NCELLS * DIM;

    cudaFuncSetAttribute(mlp_mma_kernel,
                         cudaFuncAttributeMaxDynamicSharedMemorySize, MLP_SMEM);

    zero_kernel<<<50000, 256>>>(node_out);
    attn_kernel<<<37500, 256>>>(edge_attr, node_emb, edge_index);
    mlp_mma_kernel<<<3125, 256, MLP_SMEM>>>(cell_attr, face, W1, b1, W2, b2, cell_out);
    scatter_cell_kernel<<<75000, 256>>>(cell_out, face, node_out);
    finalize_kernel<<<12500, 256>>>(node_out);
}

// round 15
// speedup vs baseline: 1.0010x; 1.0010x over previous
#include <cuda_runtime.h>
#include <math.h>
#include <cstdint>

#define NNODES 100000
#define NCELLS 200000
#define NEDGES 300000
#define DIM 128
#define THREEC (3*NCELLS)

// ---------------- scratch (static device globals: allocation-free) ----------
__device__ float g_nodesum[NNODES];
__device__ float g_counts[NNODES];
__device__ float g_nodeagg[(size_t)NNODES * DIM];

// ---------------- helpers ----------------
__device__ __forceinline__ uint32_t rna(float x) {
    uint32_t u; asm("cvt.rna.tf32.f32 %0, %1;" : "=r"(u) : "f"(x)); return u;
}
__device__ __forceinline__ float rnaf(float x) { return __uint_as_float(rna(x)); }

__device__ __forceinline__ void mma8(float c[4], const uint32_t a[4], const uint32_t b[2]) {
    asm volatile("mma.sync.aligned.m16n8k8.row.col.f32.tf32.tf32.f32 "
        "{%0,%1,%2,%3}, {%4,%5,%6,%7}, {%8,%9}, {%0,%1,%2,%3};"
        : "+f"(c[0]), "+f"(c[1]), "+f"(c[2]), "+f"(c[3])
        : "r"(a[0]), "r"(a[1]), "r"(a[2]), "r"(a[3]), "r"(b[0]), "r"(b[1]));
}

// ---------------- zero init ----------------
__global__ void zero_kernel(float* __restrict__ node_out) {
    int i = blockIdx.x * 256 + threadIdx.x;
    if (i < NNODES * DIM) { g_nodeagg[i] = 0.f; node_out[i] = 0.f; }
    if (i < NNODES)       { g_nodesum[i] = 0.f; g_counts[i] = 0.f; }
}

// ---------------- fused attention: one warp per EDGE, both directions -------
__global__ void attn_kernel(const float* __restrict__ edge_attr,
                            const float* __restrict__ node_emb,
                            const int*   __restrict__ edge_index) {
    int e    = (blockIdx.x * blockDim.x + threadIdx.x) >> 5;
    int lane = threadIdx.x & 31;
    if (e >= NEDGES) return;
    int s = __ldg(edge_index + e);
    int r = __ldg(edge_index + NEDGES + e);

    float4 a  = __ldg(((const float4*)edge_attr) + (size_t)e * 32 + lane);
    float4 bs = __ldg(((const float4*)node_emb)  + (size_t)s * 32 + lane);
    float4 br = __ldg(((const float4*)node_emb)  + (size_t)r * 32 + lane);
    float ds = a.x * bs.x + a.y * bs.y + a.z * bs.z + a.w * bs.w;
    float dr = a.x * br.x + a.y * br.y + a.z * br.z + a.w * br.w;
    #pragma unroll
    for (int off = 16; off > 0; off >>= 1) {
        ds += __shfl_xor_sync(0xffffffffu, ds, off);
        dr += __shfl_xor_sync(0xffffffffu, dr, off);
    }
    float es = expf(ds * 0.08838834764831845f);   // logits bounded, no max-shift
    float er = expf(dr * 0.08838834764831845f);

    float* dstr = g_nodeagg + (size_t)r * DIM + lane * 4;
    asm volatile("red.global.add.v4.f32 [%0], {%1,%2,%3,%4};"
                 :: "l"(dstr), "f"(a.x * er), "f"(a.y * er), "f"(a.z * er), "f"(a.w * er)
                 : "memory");
    float* dsts = g_nodeagg + (size_t)s * DIM + lane * 4;
    asm volatile("red.global.add.v4.f32 [%0], {%1,%2,%3,%4};"
                 :: "l"(dsts), "f"(a.x * es), "f"(a.y * es), "f"(a.z * es), "f"(a.w * es)
                 : "memory");
    if (lane == 0) atomicAdd(&g_nodesum[r], er);
    if (lane == 1) atomicAdd(&g_nodesum[s], es);
}

// ============================================================================
// fused MLP on tf32 mma.sync
// M-tile=64 (grid 3125 = 200000/64, no bounds checks), 256 threads, 8 warps
// (2 m-warps x 4 n-warps, warp tile 32x32), BK=32, double-buffered A/B.
// h[64x132] overlaps the A double-buffer region (union) -> 71KB SMEM/CTA,
// 2 CTAs/SM for cross-CTA latency hiding.
// ============================================================================
#define LDA 36
#define LDB 136
#define LDH 132
#define MTILE 64
#define A_CH (MTILE*LDA)            // 2304 floats per A buffer
#define B_CH (32*LDB)               // 4352 floats per B buffer
#define UNION_FLOATS (MTILE*LDH)    // 8448 >= 2*A_CH (4608)
#define SB_OFF UNION_FLOATS
#define B1_OFF (SB_OFF + 2*B_CH)
#define B2_OFF (B1_OFF + 128)
#define SF_OFF (B2_OFF + 128)
#define SINV_OFF (SF_OFF + 3*MTILE)
#define SMEM_FLOATS (SINV_OFF + 3*MTILE)
#define MLP_SMEM (SMEM_FLOATS * 4)

__global__ __launch_bounds__(256, 2)
void mlp_mma_kernel(const float* __restrict__ cell_attr, const int* __restrict__ face,
                    const float* __restrict__ W1, const float* __restrict__ b1,
                    const float* __restrict__ W2, const float* __restrict__ b2,
                    float* __restrict__ out) {
    extern __shared__ float sm[];
    float* sA   = sm;                 // 2 x A_CH (within union)
    float* sH   = sm;                 // 64 x LDH (union, after GEMM1)
    float* sB   = sm + SB_OFF;
    float* b1s  = sm + B1_OFF;
    float* b2s  = sm + B2_OFF;
    int*   sF   = (int*)(sm + SF_OFF);
    float* sInv = sm + SINV_OFF;

    const int tid  = threadIdx.x;
    const int wid  = tid >> 5, lane = tid & 31;
    const int g    = lane >> 2, tig = lane & 3;
    const int m0   = (wid & 1) * 32, n0 = (wid >> 1) * 32;
    const int rowBase = blockIdx.x * MTILE;
    const float inv3 = 1.f / 3.f;

    if (tid < 128) { b1s[tid] = b1[tid]; b2s[tid] = b2[tid]; }
    if (tid < MTILE) {
        int r = rowBase + tid;
        #pragma unroll
        for (int q = 0; q < 3; q++) {
            int f = face[q * NCELLS + r];
            sF[q * MTILE + tid] = f;
            float s = g_nodesum[f];
            sInv[q * MTILE + tid] = (s > 0.f) ? (inv3 / s) : 0.f;
        }
    }
    // sF/sInv first consumed by fetchA(c>=4), after several syncs.

    float acc[2][4][4];
    #pragma unroll
    for (int mt = 0; mt < 2; mt++)
        #pragma unroll
        for (int nt = 0; nt < 4; nt++)
            #pragma unroll
            for (int q = 0; q < 4; q++) acc[mt][nt][q] = 0.f;

    float4 pa[2], pb[4];

    // ---- A chunk (64 rows x 32 k): 512 float4, 2 per thread ----
    auto fetchA = [&](int c) {
        #pragma unroll
        for (int h = 0; h < 2; h++) {
            int j = tid + h * 256;               // [0,512)
            int m = j >> 3, kq = (j & 7) * 4;
            float4 v;
            int r = rowBase + m;
            if (c < 4) {
                v = __ldg((const float4*)(cell_attr + (size_t)r * 128 + c * 32 + kq));
            } else {
                int gk = (c - 4) * 32 + kq;
                float i0 = sInv[m], i1 = sInv[MTILE + m], i2 = sInv[2 * MTILE + m];
                float4 a0 = __ldg((const float4*)(g_nodeagg + (size_t)sF[m]           * 128 + gk));
                float4 a1 = __ldg((const float4*)(g_nodeagg + (size_t)sF[MTILE + m]   * 128 + gk));
                float4 a2 = __ldg((const float4*)(g_nodeagg + (size_t)sF[2*MTILE + m] * 128 + gk));
                v.x = a0.x * i0 + a1.x * i1 + a2.x * i2;
                v.y = a0.y * i0 + a1.y * i1 + a2.y * i2;
                v.z = a0.z * i0 + a1.z * i1 + a2.z * i2;
                v.w = a0.w * i0 + a1.w * i1 + a2.w * i2;
            }
            pa[h] = v;
        }
    };
    auto storeA = [&](int buf) {
        float* dst = sA + buf * A_CH;
        #pragma unroll
        for (int h = 0; h < 2; h++) {
            int j = tid + h * 256;
            int m = j >> 3, kq = (j & 7) * 4;
            float4 v;
            v.x = rnaf(pa[h].x); v.y = rnaf(pa[h].y);
            v.z = rnaf(pa[h].z); v.w = rnaf(pa[h].w);
            *(float4*)(dst + m * LDA + kq) = v;   // m-major STS.128, conflict-free
        }
    };
    // ---- B chunk (32 k x 128 n): 1024 float4, 4 per thread ----
    auto fetchB = [&](const float* W, int c) {
        #pragma unroll
        for (int h = 0; h < 4; h++) {
            int j = tid + h * 256;
            int k = j >> 5, n4 = (j & 31) * 4;
            pb[h] = __ldg((const float4*)(W + (size_t)(c * 32 + k) * 128 + n4));
        }
    };
    auto storeB = [&](int buf) {
        float* dst = sB + buf * B_CH;
        #pragma unroll
        for (int h = 0; h < 4; h++) {
            int j = tid + h * 256;
            int k = j >> 5, n4 = (j & 31) * 4;
            float4 v;
            v.x = rnaf(pb[h].x); v.y = rnaf(pb[h].y);
            v.z = rnaf(pb[h].z); v.w = rnaf(pb[h].w);
            *(float4*)(dst + k * LDB + n4) = v;
        }
    };
    auto mmastep = [&](const float* Ab, int lda, const float* Bb) {
        #pragma unroll
        for (int k0 = 0; k0 < 32; k0 += 8) {
            uint32_t af[2][4], bf[4][2];
            #pragma unroll
            for (int mt = 0; mt < 2; mt++) {
                const float* ar = Ab + (m0 + 16 * mt + g) * lda + k0;
                af[mt][0] = __float_as_uint(ar[tig]);
                af[mt][1] = __float_as_uint(ar[8 * lda + tig]);
                af[mt][2] = __float_as_uint(ar[tig + 4]);
                af[mt][3] = __float_as_uint(ar[8 * lda + tig + 4]);
            }
            const float* br = Bb + k0 * LDB;
            #pragma unroll
            for (int nt = 0; nt < 4; nt++) {
                int nn = n0 + 8 * nt + g;
                bf[nt][0] = __float_as_uint(br[tig * LDB + nn]);
                bf[nt][1] = __float_as_uint(br[(tig + 4) * LDB + nn]);
            }
            #pragma unroll
            for (int mt = 0; mt < 2; mt++)
                #pragma unroll
                for (int nt = 0; nt < 4; nt++)
                    mma8(acc[mt][nt], af[mt], bf[nt]);
        }
    };

    // -------- GEMM1: concat(cell_attr, cell_agg)[64x256] @ W1 --------
    fetchA(0); fetchB(W1, 0);
    storeA(0); storeB(0);
    __syncthreads();
    for (int c = 0; c < 8; c++) {
        int buf = c & 1;
        if (c < 7) { fetchA(c + 1); fetchB(W1, c + 1); }
        mmastep(sA + buf * A_CH, LDA, sB + buf * B_CH);
        if (c < 7) {
            storeA(buf ^ 1); storeB(buf ^ 1);
            __syncthreads();
        }
    }
    __syncthreads();   // all warps done reading A bufs before h overwrites union

    // -------- epilogue 1: h = relu(D1 + b1) -> sH (union), tf32-rounded --------
    #pragma unroll
    for (int mt = 0; mt < 2; mt++) {
        int row = m0 + 16 * mt + g;
        #pragma unroll
        for (int nt = 0; nt < 4; nt++) {
            int col = n0 + 8 * nt + 2 * tig;
            float bb0 = b1s[col], bb1 = b1s[col + 1];
            float2 h0, h1;
            h0.x = rnaf(fmaxf(acc[mt][nt][0] + bb0, 0.f));
            h0.y = rnaf(fmaxf(acc[mt][nt][1] + bb1, 0.f));
            h1.x = rnaf(fmaxf(acc[mt][nt][2] + bb0, 0.f));
            h1.y = rnaf(fmaxf(acc[mt][nt][3] + bb1, 0.f));
            *(float2*)(sH + row * LDH + col)       = h0;
            *(float2*)(sH + (row + 8) * LDH + col) = h1;
            acc[mt][nt][0] = 0.f; acc[mt][nt][1] = 0.f;
            acc[mt][nt][2] = 0.f; acc[mt][nt][3] = 0.f;
        }
    }
    fetchB(W2, 0);
    storeB(0);
    __syncthreads();   // covers sH writes + W2 buf0

    // -------- GEMM2: h[64x128] @ W2 --------
    for (int c = 0; c < 4; c++) {
        int buf = c & 1;
        if (c < 3) fetchB(W2, c + 1);
        mmastep(sH + c * 32, LDH, sB + buf * B_CH);
        if (c < 3) {
            storeB(buf ^ 1);
            __syncthreads();
        }
    }

    // -------- epilogue 2: out = D2 + b2 --------
    #pragma unroll
    for (int mt = 0; mt < 2; mt++) {
        int row = m0 + 16 * mt + g;
        float* o0 = out + (size_t)(rowBase + row) * 128;
        float* o1 = out + (size_t)(rowBase + row + 8) * 128;
        #pragma unroll
        for (int nt = 0; nt < 4; nt++) {
            int col = n0 + 8 * nt + 2 * tig;
            *(float2*)(o0 + col) = make_float2(acc[mt][nt][0] + b2s[col],
                                               acc[mt][nt][1] + b2s[col + 1]);
            *(float2*)(o1 + col) = make_float2(acc[mt][nt][2] + b2s[col],
                                               acc[mt][nt][3] + b2s[col + 1]);
        }
    }
}

// ---------------- scatter cell outputs to node sums + counts ----------------
__global__ void scatter_cell_kernel(const float* __restrict__ cell_out,
                                    const int*   __restrict__ face,
                                    float* __restrict__ node_out) {
    int w    = (blockIdx.x * blockDim.x + threadIdx.x) >> 5;
    int lane = threadIdx.x & 31;
    if (w >= THREEC) return;
    int node = face[w];
    int c = w;
    if (c >= NCELLS) c -= NCELLS;
    if (c >= NCELLS) c -= NCELLS;

    float4 v = __ldg(((const float4*)cell_out) + (size_t)c * 32 + lane);
    float* dst = node_out + (size_t)node * DIM + lane * 4;
    asm volatile("red.global.add.v4.f32 [%0], {%1,%2,%3,%4};"
                 :: "l"(dst), "f"(v.x), "f"(v.y), "f"(v.z), "f"(v.w)
                 : "memory");
    if (lane == 0) atomicAdd(&g_counts[node], 1.f);
}

__global__ void finalize_kernel(float* __restrict__ node_out) {
    int i = blockIdx.x * 256 + threadIdx.x;
    if (i >= NNODES * DIM / 4) return;
    float inv = 1.f / fmaxf(g_counts[i >> 5], 1.f);
    float4 v = ((float4*)node_out)[i];
    v.x *= inv; v.y *= inv; v.z *= inv; v.w *= inv;
    ((float4*)node_out)[i] = v;
}

// ---------------- launch ----------------
extern "C" void kernel_launch(void* const* d_in, const int* in_sizes, int n_in,
                              void* d_out, int out_size) {
    const float* cell_attr  = (const float*)d_in[0];
    const float* edge_attr  = (const float*)d_in[1];
    const float* node_emb   = (const float*)d_in[2];
    const int*   edge_index = (const int*)d_in[3];
    const int*   face       = (const int*)d_in[4];
    const float* W1 = (const float*)d_in[5];
    const float* b1 = (const float*)d_in[6];
    const float* W2 = (const float*)d_in[7];
    const float* b2 = (const float*)d_in[8];

    float* out      = (float*)d_out;
    float* cell_out = out;
    float* node_out = out + (size_t)NCELLS * DIM;

    cudaFuncSetAttribute(mlp_mma_kernel,
                         cudaFuncAttributeMaxDynamicSharedMemorySize, MLP_SMEM);

    zero_kernel<<<50000, 256>>>(node_out);
    attn_kernel<<<37500, 256>>>(edge_attr, node_emb, edge_index);
    mlp_mma_kernel<<<3125, 256, MLP_SMEM>>>(cell_attr, face, W1, b1, W2, b2, cell_out);
    scatter_cell_kernel<<<75000, 256>>>(cell_out, face, node_out);
    finalize_kernel<<<12500, 256>>>(node_out);
}

// round 16
// speedup vs baseline: 1.0034x; 1.0024x over previous
#include <cuda_runtime.h>
#include <math.h>
#include <cstdint>

#define NNODES 100000
#define NCELLS 200000
#define NEDGES 300000
#define DIM 128
#define THREEC (3*NCELLS)

// ---------------- scratch (static device globals: allocation-free) ----------
__device__ float g_nodesum[NNODES];
__device__ float g_counts[NNODES];
__device__ float g_nodeagg[(size_t)NNODES * DIM];

// ---------------- helpers ----------------
__device__ __forceinline__ uint32_t rna(float x) {
    uint32_t u; asm("cvt.rna.tf32.f32 %0, %1;" : "=r"(u) : "f"(x)); return u;
}
__device__ __forceinline__ float rnaf(float x) { return __uint_as_float(rna(x)); }

__device__ __forceinline__ void mma8(float c[4], const uint32_t a[4], const uint32_t b[2]) {
    asm volatile("mma.sync.aligned.m16n8k8.row.col.f32.tf32.tf32.f32 "
        "{%0,%1,%2,%3}, {%4,%5,%6,%7}, {%8,%9}, {%0,%1,%2,%3};"
        : "+f"(c[0]), "+f"(c[1]), "+f"(c[2]), "+f"(c[3])
        : "r"(a[0]), "r"(a[1]), "r"(a[2]), "r"(a[3]), "r"(b[0]), "r"(b[1]));
}

// ---------------- zero init ----------------
__global__ void zero_kernel(float* __restrict__ node_out) {
    int i = blockIdx.x * 256 + threadIdx.x;
    if (i < NNODES * DIM) { g_nodeagg[i] = 0.f; node_out[i] = 0.f; }
    if (i < NNODES)       { g_nodesum[i] = 0.f; g_counts[i] = 0.f; }
}

// ---------------- fused attention: one warp per EDGE, both directions -------
__global__ void attn_kernel(const float* __restrict__ edge_attr,
                            const float* __restrict__ node_emb,
                            const int*   __restrict__ edge_index) {
    int e    = (blockIdx.x * blockDim.x + threadIdx.x) >> 5;
    int lane = threadIdx.x & 31;
    if (e >= NEDGES) return;
    int s = __ldg(edge_index + e);
    int r = __ldg(edge_index + NEDGES + e);

    float4 a  = __ldg(((const float4*)edge_attr) + (size_t)e * 32 + lane);
    float4 bs = __ldg(((const float4*)node_emb)  + (size_t)s * 32 + lane);
    float4 br = __ldg(((const float4*)node_emb)  + (size_t)r * 32 + lane);
    float ds = a.x * bs.x + a.y * bs.y + a.z * bs.z + a.w * bs.w;
    float dr = a.x * br.x + a.y * br.y + a.z * br.z + a.w * br.w;
    #pragma unroll
    for (int off = 16; off > 0; off >>= 1) {
        ds += __shfl_xor_sync(0xffffffffu, ds, off);
        dr += __shfl_xor_sync(0xffffffffu, dr, off);
    }
    float es = expf(ds * 0.08838834764831845f);   // logits bounded, no max-shift
    float er = expf(dr * 0.08838834764831845f);

    float* dstr = g_nodeagg + (size_t)r * DIM + lane * 4;
    asm volatile("red.global.add.v4.f32 [%0], {%1,%2,%3,%4};"
                 :: "l"(dstr), "f"(a.x * er), "f"(a.y * er), "f"(a.z * er), "f"(a.w * er)
                 : "memory");
    float* dsts = g_nodeagg + (size_t)s * DIM + lane * 4;
    asm volatile("red.global.add.v4.f32 [%0], {%1,%2,%3,%4};"
                 :: "l"(dsts), "f"(a.x * es), "f"(a.y * es), "f"(a.z * es), "f"(a.w * es)
                 : "memory");
    if (lane == 0) atomicAdd(&g_nodesum[r], er);
    if (lane == 1) atomicAdd(&g_nodesum[s], es);
}

// ============================================================================
// fused MLP on tf32 mma.sync
// M-tile=64 (grid 3125 = 200000/64, no bounds checks), 256 threads, 8 warps
// (2 m-warps x 4 n-warps, warp tile 32x32), BK=32, double-buffered A/B.
// h[64x132] overlaps the A double-buffer region (union) -> 71KB SMEM/CTA,
// 2 CTAs/SM for cross-CTA latency hiding.
// ============================================================================
#define LDA 36
#define LDB 136
#define LDH 132
#define MTILE 64
#define A_CH (MTILE*LDA)            // 2304 floats per A buffer
#define B_CH (32*LDB)               // 4352 floats per B buffer
#define UNION_FLOATS (MTILE*LDH)    // 8448 >= 2*A_CH (4608)
#define SB_OFF UNION_FLOATS
#define B1_OFF (SB_OFF + 2*B_CH)
#define B2_OFF (B1_OFF + 128)
#define SF_OFF (B2_OFF + 128)
#define SINV_OFF (SF_OFF + 3*MTILE)
#define SMEM_FLOATS (SINV_OFF + 3*MTILE)
#define MLP_SMEM (SMEM_FLOATS * 4)

__global__ __launch_bounds__(256, 2)
void mlp_mma_kernel(const float* __restrict__ cell_attr, const int* __restrict__ face,
                    const float* __restrict__ W1, const float* __restrict__ b1,
                    const float* __restrict__ W2, const float* __restrict__ b2,
                    float* __restrict__ out) {
    extern __shared__ float sm[];
    float* sA   = sm;                 // 2 x A_CH (within union)
    float* sH   = sm;                 // 64 x LDH (union, after GEMM1)
    float* sB   = sm + SB_OFF;
    float* b1s  = sm + B1_OFF;
    float* b2s  = sm + B2_OFF;
    int*   sF   = (int*)(sm + SF_OFF);
    float* sInv = sm + SINV_OFF;

    const int tid  = threadIdx.x;
    const int wid  = tid >> 5, lane = tid & 31;
    const int g    = lane >> 2, tig = lane & 3;
    const int m0   = (wid & 1) * 32, n0 = (wid >> 1) * 32;
    const int rowBase = blockIdx.x * MTILE;
    const float inv3 = 1.f / 3.f;

    if (tid < 128) { b1s[tid] = b1[tid]; b2s[tid] = b2[tid]; }
    if (tid < MTILE) {
        int r = rowBase + tid;
        #pragma unroll
        for (int q = 0; q < 3; q++) {
            int f = face[q * NCELLS + r];
            sF[q * MTILE + tid] = f;
            float s = g_nodesum[f];
            sInv[q * MTILE + tid] = (s > 0.f) ? (inv3 / s) : 0.f;
        }
    }
    // sF/sInv first consumed by fetchA(c>=4), after several syncs.

    float acc[2][4][4];
    #pragma unroll
    for (int mt = 0; mt < 2; mt++)
        #pragma unroll
        for (int nt = 0; nt < 4; nt++)
            #pragma unroll
            for (int q = 0; q < 4; q++) acc[mt][nt][q] = 0.f;

    float4 pa[2], pb[4];

    // ---- A chunk (64 rows x 32 k): 512 float4, 2 per thread ----
    auto fetchA = [&](int c) {
        #pragma unroll
        for (int h = 0; h < 2; h++) {
            int j = tid + h * 256;               // [0,512)
            int m = j >> 3, kq = (j & 7) * 4;
            float4 v;
            int r = rowBase + m;
            if (c < 4) {
                v = __ldg((const float4*)(cell_attr + (size_t)r * 128 + c * 32 + kq));
            } else {
                int gk = (c - 4) * 32 + kq;
                float i0 = sInv[m], i1 = sInv[MTILE + m], i2 = sInv[2 * MTILE + m];
                float4 a0 = __ldg((const float4*)(g_nodeagg + (size_t)sF[m]           * 128 + gk));
                float4 a1 = __ldg((const float4*)(g_nodeagg + (size_t)sF[MTILE + m]   * 128 + gk));
                float4 a2 = __ldg((const float4*)(g_nodeagg + (size_t)sF[2*MTILE + m] * 128 + gk));
                v.x = a0.x * i0 + a1.x * i1 + a2.x * i2;
                v.y = a0.y * i0 + a1.y * i1 + a2.y * i2;
                v.z = a0.z * i0 + a1.z * i1 + a2.z * i2;
                v.w = a0.w * i0 + a1.w * i1 + a2.w * i2;
            }
            pa[h] = v;
        }
    };
    auto storeA = [&](int buf) {
        float* dst = sA + buf * A_CH;
        #pragma unroll
        for (int h = 0; h < 2; h++) {
            int j = tid + h * 256;
            int m = j >> 3, kq = (j & 7) * 4;
            float4 v;
            v.x = rnaf(pa[h].x); v.y = rnaf(pa[h].y);
            v.z = rnaf(pa[h].z); v.w = rnaf(pa[h].w);
            *(float4*)(dst + m * LDA + kq) = v;   // m-major STS.128, conflict-free
        }
    };
    // ---- B chunk (32 k x 128 n): 1024 float4, 4 per thread ----
    auto fetchB = [&](const float* W, int c) {
        #pragma unroll
        for (int h = 0; h < 4; h++) {
            int j = tid + h * 256;
            int k = j >> 5, n4 = (j & 31) * 4;
            pb[h] = __ldg((const float4*)(W + (size_t)(c * 32 + k) * 128 + n4));
        }
    };
    auto storeB = [&](int buf) {
        float* dst = sB + buf * B_CH;
        #pragma unroll
        for (int h = 0; h < 4; h++) {
            int j = tid + h * 256;
            int k = j >> 5, n4 = (j & 31) * 4;
            float4 v;
            v.x = rnaf(pb[h].x); v.y = rnaf(pb[h].y);
            v.z = rnaf(pb[h].z); v.w = rnaf(pb[h].w);
            *(float4*)(dst + k * LDB + n4) = v;
        }
    };
    auto mmastep = [&](const float* Ab, int lda, const float* Bb) {
        #pragma unroll
        for (int k0 = 0; k0 < 32; k0 += 8) {
            uint32_t af[2][4], bf[4][2];
            #pragma unroll
            for (int mt = 0; mt < 2; mt++) {
                const float* ar = Ab + (m0 + 16 * mt + g) * lda + k0;
                af[mt][0] = __float_as_uint(ar[tig]);
                af[mt][1] = __float_as_uint(ar[8 * lda + tig]);
                af[mt][2] = __float_as_uint(ar[tig + 4]);
                af[mt][3] = __float_as_uint(ar[8 * lda + tig + 4]);
            }
            const float* br = Bb + k0 * LDB;
            #pragma unroll
            for (int nt = 0; nt < 4; nt++) {
                int nn = n0 + 8 * nt + g;
                bf[nt][0] = __float_as_uint(br[tig * LDB + nn]);
                bf[nt][1] = __float_as_uint(br[(tig + 4) * LDB + nn]);
            }
            #pragma unroll
            for (int mt = 0; mt < 2; mt++)
                #pragma unroll
                for (int nt = 0; nt < 4; nt++)
                    mma8(acc[mt][nt], af[mt], bf[nt]);
        }
    };

    // -------- GEMM1: concat(cell_attr, cell_agg)[64x256] @ W1 --------
    fetchA(0); fetchB(W1, 0);
    storeA(0); storeB(0);
    __syncthreads();
    for (int c = 0; c < 8; c++) {
        int buf = c & 1;
        if (c < 7) { fetchA(c + 1); fetchB(W1, c + 1); }
        mmastep(sA + buf * A_CH, LDA, sB + buf * B_CH);
        if (c < 7) {
            storeA(buf ^ 1); storeB(buf ^ 1);
            __syncthreads();
        }
    }
    __syncthreads();   // all warps done reading A bufs before h overwrites union

    // -------- epilogue 1: h = relu(D1 + b1) -> sH (union), tf32-rounded --------
    #pragma unroll
    for (int mt = 0; mt < 2; mt++) {
        int row = m0 + 16 * mt + g;
        #pragma unroll
        for (int nt = 0; nt < 4; nt++) {
            int col = n0 + 8 * nt + 2 * tig;
            float bb0 = b1s[col], bb1 = b1s[col + 1];
            float2 h0, h1;
            h0.x = rnaf(fmaxf(acc[mt][nt][0] + bb0, 0.f));
            h0.y = rnaf(fmaxf(acc[mt][nt][1] + bb1, 0.f));
            h1.x = rnaf(fmaxf(acc[mt][nt][2] + bb0, 0.f));
            h1.y = rnaf(fmaxf(acc[mt][nt][3] + bb1, 0.f));
            *(float2*)(sH + row * LDH + col)       = h0;
            *(float2*)(sH + (row + 8) * LDH + col) = h1;
            acc[mt][nt][0] = 0.f; acc[mt][nt][1] = 0.f;
            acc[mt][nt][2] = 0.f; acc[mt][nt][3] = 0.f;
        }
    }
    fetchB(W2, 0);
    storeB(0);
    __syncthreads();   // covers sH writes + W2 buf0

    // -------- GEMM2: h[64x128] @ W2 --------
    for (int c = 0; c < 4; c++) {
        int buf = c & 1;
        if (c < 3) fetchB(W2, c + 1);
        mmastep(sH + c * 32, LDH, sB + buf * B_CH);
        if (c < 3) {
            storeB(buf ^ 1);
            __syncthreads();
        }
    }

    // -------- epilogue 2: out = D2 + b2 --------
    #pragma unroll
    for (int mt = 0; mt < 2; mt++) {
        int row = m0 + 16 * mt + g;
        float* o0 = out + (size_t)(rowBase + row) * 128;
        float* o1 = out + (size_t)(rowBase + row + 8) * 128;
        #pragma unroll
        for (int nt = 0; nt < 4; nt++) {
            int col = n0 + 8 * nt + 2 * tig;
            *(float2*)(o0 + col) = make_float2(acc[mt][nt][0] + b2s[col],
                                               acc[mt][nt][1] + b2s[col + 1]);
            *(float2*)(o1 + col) = make_float2(acc[mt][nt][2] + b2s[col],
                                               acc[mt][nt][3] + b2s[col + 1]);
        }
    }
}

// ---------------- scatter cell outputs to node sums + counts ----------------
__global__ void scatter_cell_kernel(const float* __restrict__ cell_out,
                                    const int*   __restrict__ face,
                                    float* __restrict__ node_out) {
    int w    = (blockIdx.x * blockDim.x + threadIdx.x) >> 5;
    int lane = threadIdx.x & 31;
    if (w >= THREEC) return;
    int node = face[w];
    int c = w;
    if (c >= NCELLS) c -= NCELLS;
    if (c >= NCELLS) c -= NCELLS;

    float4 v = __ldg(((const float4*)cell_out) + (size_t)c * 32 + lane);
    float* dst = node_out + (size_t)node * DIM + lane * 4;
    asm volatile("red.global.add.v4.f32 [%0], {%1,%2,%3,%4};"
                 :: "l"(dst), "f"(v.x), "f"(v.y), "f"(v.z), "f"(v.w)
                 : "memory");
    if (lane == 0) atomicAdd(&g_counts[node], 1.f);
}

__global__ void finalize_kernel(float* __restrict__ node_out) {
    int i = blockIdx.x * 256 + threadIdx.x;
    if (i >= NNODES * DIM / 4) return;
    float inv = 1.f / fmaxf(g_counts[i >> 5], 1.f);
    float4 v = ((float4*)node_out)[i];
    v.x *= inv; v.y *= inv; v.z *= inv; v.w *= inv;
    ((float4*)node_out)[i] = v;
}

// ---------------- launch ----------------
extern "C" void kernel_launch(void* const* d_in, const int* in_sizes, int n_in,
                              void* d_out, int out_size) {
    const float* cell_attr  = (const float*)d_in[0];
    const float* edge_attr  = (const float*)d_in[1];
    const float* node_emb   = (const float*)d_in[2];
    const int*   edge_index = (const int*)d_in[3];
    const int*   face       = (const int*)d_in[4];
    const float* W1 = (const float*)d_in[5];
    const float* b1 = (const float*)d_in[6];
    const float* W2 = (const float*)d_in[7];
    const float* b2 = (const float*)d_in[8];

    float* out      = (float*)d_out;
    float* cell_out = out;
    float* node_out = out + (size_t)NCELLS * DIM;

    cudaFuncSetAttribute(mlp_mma_kernel,
                         cudaFuncAttributeMaxDynamicSharedMemorySize, MLP_SMEM);

    zero_kernel<<<50000, 256>>>(node_out);
    attn_kernel<<<37500, 256>>>(edge_attr, node_emb, edge_index);
    mlp_mma_kernel<<<3125, 256, MLP_SMEM>>>(cell_attr, face, W1, b1, W2, b2, cell_out);
    scatter_cell_kernel<<<75000, 256>>>(cell_out, face, node_out);
    finalize_kernel<<<12500, 256>>>(node_out);
}